// round 4
// baseline (speedup 1.0000x reference)
#include <cuda_runtime.h>
#include <cstdint>
#include <math.h>

#define DEV_INLINE __device__ __forceinline__

// Problem dims (fixed by the dataset)
constexpr int B_ = 128, T_ = 512, F_ = 512, M_ = 512;
constexpr float LN_EPS = 1e-5f;

// GEMM tiling: CTA 256(m) x 128(f) x 32(k); 16 warps of 64x32
constexpr int BM = 256, BN = 128, BK = 32;
constexpr int NKC = T_ / BK;     // 16 k-chunks
constexpr int THREADS = 512;

// Stage sizes in floats
constexpr int A_STAGE = BM * BK;                  // 8192 floats (frag-order W)
constexpr int B_ROWPAD = 132;                     // 128 + 4 pad (16B, cp.async-safe)
constexpr int B_STAGE = BK * B_ROWPAD;            // 4224 floats (natural x tile)
constexpr int STAGE   = A_STAGE + B_STAGE;        // 12416 floats
constexpr int SMEM_BYTES = 2 * STAGE * 4;         // 99328 B (dynamic)

// Device scratch (no allocation allowed)
__device__ float g_mean[B_ * F_];
__device__ float g_rstd[B_ * F_];
__device__ float g_Wfrag[M_ * T_];                // 1MB, frag-order tf32

// ---------------- helpers ----------------
DEV_INLINE uint32_t smem_u32(const void* p) {
    uint32_t a;
    asm("{ .reg .u64 t; cvta.to.shared.u64 t, %1; cvt.u32.u64 %0, t; }"
        : "=r"(a) : "l"(p));
    return a;
}

DEV_INLINE float to_tf32(float f) {
    float o;
    asm("cvt.rna.tf32.f32 %0, %1;" : "=f"(o) : "f"(f));
    return o;
}

DEV_INLINE void cp_async16(uint32_t dst_smem, const void* src) {
    asm volatile(
        "{\n\t.reg .u64 g;\n\tcvta.to.global.u64 g, %1;\n\t"
        "cp.async.cg.shared.global [%0], [g], 16;\n\t}"
        :: "r"(dst_smem), "l"(src));
}
DEV_INLINE void cp_commit() { asm volatile("cp.async.commit_group;"); }
template <int N> DEV_INLINE void cp_wait() {
    asm volatile("cp.async.wait_group %0;" :: "n"(N));
}

DEV_INLINE void mma_tf32(float* c, const uint32_t* a, const uint32_t* b) {
    asm volatile(
        "mma.sync.aligned.m16n8k8.row.col.f32.tf32.tf32.f32 "
        "{%0,%1,%2,%3}, {%4,%5,%6,%7}, {%8,%9}, {%0,%1,%2,%3};"
        : "+f"(c[0]), "+f"(c[1]), "+f"(c[2]), "+f"(c[3])
        : "r"(a[0]), "r"(a[1]), "r"(a[2]), "r"(a[3]), "r"(b[0]), "r"(b[1]));
}

DEV_INLINE float gelu_exact(float v) {
    return 0.5f * v * (1.0f + erff(v * 0.70710678118654752f));
}

// ---------------- kernel 1: LN stats over T per (b, f) ----------------
__global__ __launch_bounds__(256) void ln_stats_kernel(const float* __restrict__ x) {
    int b = blockIdx.x >> 1;
    int f = ((blockIdx.x & 1) << 8) + threadIdx.x;
    const float* xp = x + (size_t)b * T_ * F_ + f;
    float s = 0.f, ss = 0.f;
#pragma unroll 8
    for (int t = 0; t < T_; t++) {
        float v = xp[(size_t)t * F_];
        s += v;
        ss += v * v;
    }
    float mean = s * (1.0f / T_);
    float var = ss * (1.0f / T_) - mean * mean;
    g_mean[b * F_ + f] = mean;
    g_rstd[b * F_ + f] = rsqrtf(fmaxf(var, 0.0f) + LN_EPS);
}

// ---------------- kernel 2: pack W into A-fragment order ----------------
// Layout: [m16 (32)][kc (16)][kstep (4)][lane (32)][4]
// lane = g*4+tig; regs: {W[g][tig], W[g+8][tig], W[g][tig+4], W[g+8][tig+4]}
__global__ __launch_bounds__(256) void pack_w_kernel(const float* __restrict__ W) {
    int lin = blockIdx.x * 256 + threadIdx.x;       // 65536 float4s
    int lane = lin & 31;
    int kstep = (lin >> 5) & 3;
    int kc = (lin >> 7) & 15;
    int m16 = lin >> 11;
    int g = lane >> 2, tig = lane & 3;
    int mr = m16 * 16 + g;
    int tc = kc * 32 + kstep * 8 + tig;
    float4 v;
    v.x = to_tf32(W[(size_t)mr * T_ + tc]);
    v.y = to_tf32(W[(size_t)(mr + 8) * T_ + tc]);
    v.z = to_tf32(W[(size_t)mr * T_ + tc + 4]);
    v.w = to_tf32(W[(size_t)(mr + 8) * T_ + tc + 4]);
    reinterpret_cast<float4*>(g_Wfrag)[lin] = v;
}

// ---------------- kernel 3: fused normalize + tf32 GEMM + GELU + residual ----------------
__global__ __launch_bounds__(THREADS, 1)
void timemix_gemm_kernel(const float* __restrict__ x,
                         const float* __restrict__ gamma,
                         const float* __restrict__ beta,
                         const float* __restrict__ bvec,
                         float* __restrict__ out) {
    extern __shared__ float smem[];
    __shared__ float s_gamma[T_], s_beta[T_];

    const int tid = threadIdx.x;
    const int wid = tid >> 5, lane = tid & 31;
    const int wm = wid & 3, wn = wid >> 2;          // 4 x 4 warp grid (64m x 32f)
    const int g = lane >> 2, tig = lane & 3;
    const int bm = blockIdx.x;                      // 0..1 (m tiles)
    const int ft = blockIdx.y;                      // 0..3 (f tiles)
    const int b = blockIdx.z;

    const uint32_t smem_base = smem_u32(smem);

    // stage gamma/beta once
    s_gamma[tid] = gamma[tid];
    s_beta[tid]  = beta[tid];

    // per-lane LN params for the 4 f-columns this lane owns (f = fw + j*8 + g)
    const int fw = ft * 128 + wn * 32;
    float mu_r[4], rs_r[4];
#pragma unroll
    for (int j = 0; j < 4; j++) {
        mu_r[j] = g_mean[b * F_ + fw + j * 8 + g];
        rs_r[j] = g_rstd[b * F_ + fw + j * 8 + g];
    }

    // stage loader: A = frag-order W, B = natural x tile [32t][128f + pad]
    auto load_stage = [&](int kc, int stg) {
        uint32_t sA = smem_base + stg * (STAGE * 4);
        uint32_t sB = sA + A_STAGE * 4;
        const int k0 = kc * BK;
#pragma unroll
        for (int r = 0; r < 4; r++) {               // A: 2048 float4s
            int i = tid + r * THREADS;
            int m16l = i >> 7;
            int off = i & 127;
            const float* src = g_Wfrag + ((size_t)(bm * 16 + m16l) * 16 + kc) * 512 + off * 4;
            cp_async16(sA + (m16l * 512 + off * 4) * 4, src);
        }
#pragma unroll
        for (int r = 0; r < 2; r++) {               // B: 1024 float4s
            int i = tid + r * THREADS;
            int t = i >> 5;
            int c = i & 31;
            const float* src = x + ((size_t)b * T_ + k0 + t) * F_ + ft * 128 + c * 4;
            cp_async16(sB + t * (B_ROWPAD * 4) + c * 16, src);
        }
        cp_commit();
    };

    float acc[4][4][4];
#pragma unroll
    for (int i = 0; i < 4; i++)
#pragma unroll
        for (int j = 0; j < 4; j++)
#pragma unroll
            for (int r = 0; r < 4; r++) acc[i][j][r] = 0.0f;

    load_stage(0, 0);
    __syncthreads();   // ensure s_gamma/s_beta visible (first-iter use)

    for (int kc = 0; kc < NKC; kc++) {
        if (kc + 1 < NKC) {
            load_stage(kc + 1, (kc + 1) & 1);
            cp_wait<1>();
        } else {
            cp_wait<0>();
        }
        __syncthreads();

        const float* sA = smem + (kc & 1) * STAGE;
        const float* sB = sA + A_STAGE;
        const int k0 = kc * BK;

#pragma unroll
        for (int kstep = 0; kstep < 4; kstep++) {
            // A fragments (frag-order, conflict-free LDS.128)
            uint32_t a[4][4];
#pragma unroll
            for (int i = 0; i < 4; i++) {
                float4 v = *reinterpret_cast<const float4*>(
                    sA + ((wm * 4 + i) * 4 + kstep) * 128 + lane * 4);
                a[i][0] = __float_as_uint(v.x);
                a[i][1] = __float_as_uint(v.y);
                a[i][2] = __float_as_uint(v.z);
                a[i][3] = __float_as_uint(v.w);
            }
            // B fragments: read natural tile, normalize on the fly
            const int t0 = kstep * 8 + tig;
            const float ga0 = s_gamma[k0 + t0],     be0 = s_beta[k0 + t0];
            const float ga1 = s_gamma[k0 + t0 + 4], be1 = s_beta[k0 + t0 + 4];
            uint32_t bfr[4][2];
#pragma unroll
            for (int j = 0; j < 4; j++) {
                const int fl = wn * 32 + j * 8 + g;
                float v0 = sB[t0 * B_ROWPAD + fl];
                float v1 = sB[(t0 + 4) * B_ROWPAD + fl];
                float s0 = rs_r[j] * ga0;
                float c0 = fmaf(-mu_r[j], s0, be0);
                float s1 = rs_r[j] * ga1;
                float c1 = fmaf(-mu_r[j], s1, be1);
                bfr[j][0] = __float_as_uint(to_tf32(fmaf(v0, s0, c0)));
                bfr[j][1] = __float_as_uint(to_tf32(fmaf(v1, s1, c1)));
            }
#pragma unroll
            for (int i = 0; i < 4; i++)
#pragma unroll
                for (int j = 0; j < 4; j++)
                    mma_tf32(acc[i][j], a[i], bfr[j]);
        }
        __syncthreads();
    }

    // ---- epilogue: bias + exact GELU + residual ----
    const int m_warp = bm * 256 + wm * 64;
#pragma unroll
    for (int i = 0; i < 4; i++) {
#pragma unroll
        for (int h = 0; h < 2; h++) {
            int m = m_warp + i * 16 + g + 8 * h;
            float bv = bvec[m];
            const float* xr = x + ((size_t)b * M_ + m) * F_ + fw;
            float* yr = out + ((size_t)b * M_ + m) * F_ + fw;
#pragma unroll
            for (int j = 0; j < 4; j++) {
                int fo = j * 8 + tig * 2;
                float2 xv = *reinterpret_cast<const float2*>(xr + fo);
                float2 o;
                o.x = gelu_exact(acc[i][j][2 * h + 0] + bv) + xv.x;
                o.y = gelu_exact(acc[i][j][2 * h + 1] + bv) + xv.y;
                *reinterpret_cast<float2*>(yr + fo) = o;
            }
        }
    }
}

// ---------------- launch ----------------
extern "C" void kernel_launch(void* const* d_in, const int* in_sizes, int n_in,
                              void* d_out, int out_size) {
    const float* x     = (const float*)d_in[0];
    const float* gamma = (const float*)d_in[1];
    const float* beta  = (const float*)d_in[2];
    const float* W     = (const float*)d_in[3];
    const float* bvec  = (const float*)d_in[4];
    float* out = (float*)d_out;

    cudaFuncSetAttribute(timemix_gemm_kernel,
                         cudaFuncAttributeMaxDynamicSharedMemorySize, SMEM_BYTES);

    ln_stats_kernel<<<(B_ * F_) / 256, 256>>>(x);
    pack_w_kernel<<<(M_ * T_ / 4) / 256, 256>>>(W);
    {
        dim3 grid(M_ / BM, F_ / BN, B_);   // (2, 4, 128)
        timemix_gemm_kernel<<<grid, THREADS, SMEM_BYTES>>>(x, gamma, beta, bvec, out);
    }
}

// round 5
// speedup vs baseline: 1.1264x; 1.1264x over previous
#include <cuda_runtime.h>
#include <cstdint>
#include <math.h>

#define DEV_INLINE __device__ __forceinline__

// Problem dims (fixed by the dataset)
constexpr int B_ = 128, T_ = 512, F_ = 512, M_ = 512;
constexpr float LN_EPS = 1e-5f;

// GEMM tiling: CTA 256(m) x 128(f) x 32(k); 8 warps of 64x64
constexpr int BM = 256, BN = 128, BK = 32;
constexpr int NKC = T_ / BK;     // 16 k-chunks
constexpr int THREADS = 256;
constexpr int NSTAGE = 3;

// Stage sizes in floats
constexpr int A_STAGE = BM * BK;                 // 8192 (frag-order W)
constexpr int B_STAGE = BN * BK;                 // 4096 (paired frag-order xn)
constexpr int STAGE   = A_STAGE + B_STAGE;       // 12288 floats = 48KB
constexpr int SMEM_BYTES = NSTAGE * STAGE * 4;   // 147456 B

// Device scratch (no allocation allowed)
__device__ float g_s[2][B_ * F_];                // partial sums (T halves)
__device__ float g_ss[2][B_ * F_];
__device__ float g_Wfrag[M_ * T_];               // 1MB, frag-order tf32
__device__ float g_Bfrag[(size_t)B_ * T_ * F_];  // 128MB, paired frag-order tf32

// ---------------- helpers ----------------
DEV_INLINE uint32_t smem_u32(const void* p) {
    uint32_t a;
    asm("{ .reg .u64 t; cvta.to.shared.u64 t, %1; cvt.u32.u64 %0, t; }"
        : "=r"(a) : "l"(p));
    return a;
}

DEV_INLINE float to_tf32(float f) {
    float o;
    asm("cvt.rna.tf32.f32 %0, %1;" : "=f"(o) : "f"(f));
    return o;
}

DEV_INLINE void cp_async16(uint32_t dst_smem, const void* src) {
    asm volatile(
        "{\n\t.reg .u64 g;\n\tcvta.to.global.u64 g, %1;\n\t"
        "cp.async.cg.shared.global [%0], [g], 16;\n\t}"
        :: "r"(dst_smem), "l"(src));
}
DEV_INLINE void cp_commit() { asm volatile("cp.async.commit_group;"); }
template <int N> DEV_INLINE void cp_wait() {
    asm volatile("cp.async.wait_group %0;" :: "n"(N));
}

DEV_INLINE void mma_tf32(float* c, const uint32_t* a, uint32_t b0, uint32_t b1) {
    asm volatile(
        "mma.sync.aligned.m16n8k8.row.col.f32.tf32.tf32.f32 "
        "{%0,%1,%2,%3}, {%4,%5,%6,%7}, {%8,%9}, {%0,%1,%2,%3};"
        : "+f"(c[0]), "+f"(c[1]), "+f"(c[2]), "+f"(c[3])
        : "r"(a[0]), "r"(a[1]), "r"(a[2]), "r"(a[3]), "r"(b0), "r"(b1));
}

DEV_INLINE float gelu_exact(float v) {
    return 0.5f * v * (1.0f + erff(v * 0.70710678118654752f));
}

// ---------------- kernel 1: LN partial sums (T split in 2) ----------------
__global__ __launch_bounds__(256) void ln_partial_kernel(const float* __restrict__ x) {
    const int th = blockIdx.x & 1;             // T half
    const int fc = (blockIdx.x >> 1) & 1;      // f chunk of 256
    const int b  = blockIdx.x >> 2;
    const int f  = fc * 256 + threadIdx.x;
    const float* xp = x + ((size_t)b * T_ + th * 256) * F_ + f;
    float s = 0.f, ss = 0.f;
#pragma unroll 8
    for (int t = 0; t < 256; t++) {
        float v = xp[(size_t)t * F_];
        s += v;
        ss += v * v;
    }
    g_s[th][b * F_ + f]  = s;
    g_ss[th][b * F_ + f] = ss;
}

// ---------------- kernel 2: pack W into A-fragment order ----------------
// Layout: [m16 (32)][kc (16)][kstep (4)][lane (32)][4]
__global__ __launch_bounds__(256) void pack_w_kernel(const float* __restrict__ W) {
    int lin = blockIdx.x * 256 + threadIdx.x;       // 65536 float4s
    int lane = lin & 31;
    int kstep = (lin >> 5) & 3;
    int kc = (lin >> 7) & 15;
    int m16 = lin >> 11;
    int g = lane >> 2, tig = lane & 3;
    int mr = m16 * 16 + g;
    int tc = kc * 32 + kstep * 8 + tig;
    float4 v;
    v.x = to_tf32(W[(size_t)mr * T_ + tc]);
    v.y = to_tf32(W[(size_t)(mr + 8) * T_ + tc]);
    v.z = to_tf32(W[(size_t)mr * T_ + tc + 4]);
    v.w = to_tf32(W[(size_t)(mr + 8) * T_ + tc + 4]);
    reinterpret_cast<float4*>(g_Wfrag)[lin] = v;
}

// ---------------- kernel 3: normalize + transpose into PAIRED B-fragment order ----------
// Layout per (b, ft, kc): [np (8)][kstep (4)][lane (32)][4]
// float4 = { xn[t0][f0], xn[t0+4][f0], xn[t0][f1], xn[t0+4][f1] }
//   t0 = kstep*8 + (lane&3), f0 = np*16 + (lane>>2), f1 = f0 + 8   (f local to ft*128)
__global__ __launch_bounds__(256) void pack_xn_kernel(const float* __restrict__ x,
                                                      const float* __restrict__ gamma,
                                                      const float* __restrict__ beta) {
    __shared__ float s[32][132];   // [t_local][f_local], padded
    __shared__ float s_mu[128], s_rs[128];
    const int kc = blockIdx.x, ft = blockIdx.y, b = blockIdx.z;
    const int tid = threadIdx.x;

    // combine LN partials for this block's 128 f's
    if (tid < 128) {
        int idx = b * F_ + ft * 128 + tid;
        float sm = g_s[0][idx] + g_s[1][idx];
        float sq = g_ss[0][idx] + g_ss[1][idx];
        float mean = sm * (1.0f / T_);
        float var = sq * (1.0f / T_) - mean * mean;
        s_mu[tid] = mean;
        s_rs[tid] = rsqrtf(fmaxf(var, 0.0f) + LN_EPS);
    }
    __syncthreads();

    // load + normalize (coalesced over f)
#pragma unroll
    for (int r = 0; r < 4; r++) {
        int i4 = tid + r * 256;
        int tl = i4 >> 5;
        int f4 = (i4 & 31) << 2;
        int gt = kc * 32 + tl;
        float4 v = *reinterpret_cast<const float4*>(
            x + ((size_t)b * T_ + gt) * F_ + ft * 128 + f4);
        float ga = gamma[gt], be = beta[gt];
        s[tl][f4 + 0] = to_tf32((v.x - s_mu[f4 + 0]) * s_rs[f4 + 0] * ga + be);
        s[tl][f4 + 1] = to_tf32((v.y - s_mu[f4 + 1]) * s_rs[f4 + 1] * ga + be);
        s[tl][f4 + 2] = to_tf32((v.z - s_mu[f4 + 2]) * s_rs[f4 + 2] * ga + be);
        s[tl][f4 + 3] = to_tf32((v.w - s_mu[f4 + 3]) * s_rs[f4 + 3] * ga + be);
    }
    __syncthreads();

    // write paired frag order (coalesced float4)
    float* dst = g_Bfrag + (((size_t)b * 4 + ft) * 16 + kc) * 4096;
#pragma unroll
    for (int r = 0; r < 4; r++) {
        int o4 = tid + r * 256;                 // 1024 float4s
        int np = o4 >> 7;
        int rem = o4 & 127;
        int kstep = rem >> 5;
        int lane = rem & 31;
        int g = lane >> 2, tig = lane & 3;
        int t0 = kstep * 8 + tig;
        int f0 = np * 16 + g;
        float4 v;
        v.x = s[t0][f0];
        v.y = s[t0 + 4][f0];
        v.z = s[t0][f0 + 8];
        v.w = s[t0 + 4][f0 + 8];
        reinterpret_cast<float4*>(dst)[o4] = v;
    }
}

// ---------------- kernel 4: tf32 GEMM + bias + GELU + residual ----------------
__global__ __launch_bounds__(THREADS, 1)
void timemix_gemm_kernel(const float* __restrict__ x,
                         const float* __restrict__ bvec,
                         float* __restrict__ out) {
    extern __shared__ float smem[];
    const int tid = threadIdx.x;
    const int wid = tid >> 5, lane = tid & 31;
    const int wm = wid & 3, wn = wid >> 2;          // 4 x 2 warp grid (64m x 64f)
    const int bm = blockIdx.x;                      // 0..1
    const int ft = blockIdx.y;                      // 0..3
    const int b = blockIdx.z;

    const uint32_t smem_base = smem_u32(smem);
    const float* Bsrc_base = g_Bfrag + (((size_t)b * 4 + ft) * 16) * 4096;

    auto load_stage = [&](int kc) {
        uint32_t sA = smem_base + (kc % NSTAGE) * (STAGE * 4);
        uint32_t sB = sA + A_STAGE * 4;
#pragma unroll
        for (int r = 0; r < 8; r++) {               // A: 2048 float4s
            int i = tid + r * 256;
            int m16l = i >> 7;
            int off = i & 127;
            const float* src = g_Wfrag + ((size_t)(bm * 16 + m16l) * 16 + kc) * 512 + off * 4;
            cp_async16(sA + (m16l * 512 + off * 4) * 4, src);
        }
        const float* Bsrc = Bsrc_base + (size_t)kc * 4096;
#pragma unroll
        for (int r = 0; r < 4; r++) {               // B: 1024 float4s
            int i = tid + r * 256;
            cp_async16(sB + i * 16, Bsrc + i * 4);
        }
        cp_commit();
    };

    float acc[4][8][4];
#pragma unroll
    for (int i = 0; i < 4; i++)
#pragma unroll
        for (int j = 0; j < 8; j++)
#pragma unroll
            for (int r = 0; r < 4; r++) acc[i][j][r] = 0.0f;

    load_stage(0);
    load_stage(1);

    for (int kc = 0; kc < NKC; kc++) {
        if (kc + 1 < NKC) cp_wait<1>(); else cp_wait<0>();
        __syncthreads();

        const float* sA = smem + (kc % NSTAGE) * STAGE;
        const float* sB = sA + A_STAGE;

#pragma unroll
        for (int kstep = 0; kstep < 4; kstep++) {
            uint32_t a[4][4];
#pragma unroll
            for (int i = 0; i < 4; i++) {
                float4 v = *reinterpret_cast<const float4*>(
                    sA + ((wm * 4 + i) * 4 + kstep) * 128 + lane * 4);
                a[i][0] = __float_as_uint(v.x);
                a[i][1] = __float_as_uint(v.y);
                a[i][2] = __float_as_uint(v.z);
                a[i][3] = __float_as_uint(v.w);
            }
            uint32_t bfr[4][4];
#pragma unroll
            for (int jp = 0; jp < 4; jp++) {
                float4 v = *reinterpret_cast<const float4*>(
                    sB + ((wn * 4 + jp) * 4 + kstep) * 128 + lane * 4);
                bfr[jp][0] = __float_as_uint(v.x);
                bfr[jp][1] = __float_as_uint(v.y);
                bfr[jp][2] = __float_as_uint(v.z);
                bfr[jp][3] = __float_as_uint(v.w);
            }
#pragma unroll
            for (int i = 0; i < 4; i++)
#pragma unroll
                for (int jp = 0; jp < 4; jp++) {
                    mma_tf32(acc[i][2 * jp + 0], a[i], bfr[jp][0], bfr[jp][1]);
                    mma_tf32(acc[i][2 * jp + 1], a[i], bfr[jp][2], bfr[jp][3]);
                }
        }

        // prefetch kc+2 AFTER compute (3-stage, single barrier per iter is race-free)
        if (kc + 2 < NKC) load_stage(kc + 2);
    }

    // ---- epilogue: bias + exact GELU + residual ----
    const int g = lane >> 2, tig = lane & 3;
    const int m_warp = bm * 256 + wm * 64;
    const int f_warp = ft * 128 + wn * 64;
#pragma unroll
    for (int i = 0; i < 4; i++) {
#pragma unroll
        for (int h = 0; h < 2; h++) {
            int m = m_warp + i * 16 + g + 8 * h;
            float bv = bvec[m];
            const float* xr = x + ((size_t)b * M_ + m) * F_ + f_warp;
            float* yr = out + ((size_t)b * M_ + m) * F_ + f_warp;
#pragma unroll
            for (int j = 0; j < 8; j++) {
                int fo = j * 8 + tig * 2;
                float2 xv = *reinterpret_cast<const float2*>(xr + fo);
                float2 o;
                o.x = gelu_exact(acc[i][j][2 * h + 0] + bv) + xv.x;
                o.y = gelu_exact(acc[i][j][2 * h + 1] + bv) + xv.y;
                *reinterpret_cast<float2*>(yr + fo) = o;
            }
        }
    }
}

// ---------------- launch ----------------
extern "C" void kernel_launch(void* const* d_in, const int* in_sizes, int n_in,
                              void* d_out, int out_size) {
    const float* x     = (const float*)d_in[0];
    const float* gamma = (const float*)d_in[1];
    const float* beta  = (const float*)d_in[2];
    const float* W     = (const float*)d_in[3];
    const float* bvec  = (const float*)d_in[4];
    float* out = (float*)d_out;

    cudaFuncSetAttribute(timemix_gemm_kernel,
                         cudaFuncAttributeMaxDynamicSharedMemorySize, SMEM_BYTES);

    ln_partial_kernel<<<B_ * 2 * 2, 256>>>(x);
    pack_w_kernel<<<(M_ * T_ / 4) / 256, 256>>>(W);
    {
        dim3 grid(NKC, F_ / 128, B_);
        pack_xn_kernel<<<grid, 256>>>(x, gamma, beta);
    }
    {
        dim3 grid(M_ / BM, F_ / BN, B_);   // (2, 4, 128)
        timemix_gemm_kernel<<<grid, THREADS, SMEM_BYTES>>>(x, bvec, out);
    }
}

// round 6
// speedup vs baseline: 1.6937x; 1.5037x over previous
#include <cuda_runtime.h>
#include <cuda_fp16.h>
#include <cstdint>
#include <math.h>

#define DEV_INLINE __device__ __forceinline__

// Problem dims (fixed by the dataset)
constexpr int B_ = 128, T_ = 512, F_ = 512, M_ = 512;
constexpr float LN_EPS = 1e-5f;

// GEMM tiling: CTA 128(m) x 128(f) x 32(k); 8 warps of 32x64; fp16 mma k16
constexpr int BM = 128, BN = 128, BK = 32;
constexpr int NKC = T_ / BK;     // 16 k-chunks
constexpr int THREADS = 256;
constexpr int NSTAGE = 4;

// Stage sizes in BYTES (fp16 operands)
constexpr int A_STAGE_B = BM * BK * 2;            // 8192 B (frag-order W fp16)
constexpr int B_STAGE_B = BN * BK * 2;            // 8192 B (paired frag-order xn fp16)
constexpr int STAGE_B   = A_STAGE_B + B_STAGE_B;  // 16 KB
constexpr int SMEM_BYTES = NSTAGE * STAGE_B;      // 64 KB

// Device scratch (no allocation allowed)
__device__ float g_s[2][B_ * F_];                 // LN partial sums (T halves)
__device__ float g_ss[2][B_ * F_];
__device__ uint4 g_WfragH[32 * 16 * 2 * 32];      // 512KB: [m16][kc][kstep][lane]
__device__ uint4 g_BfragH[(size_t)B_ * 4 * 16 * 512];  // 64MB: [b][ft][kc][np][kstep][lane]

// ---------------- helpers ----------------
DEV_INLINE uint32_t smem_u32(const void* p) {
    uint32_t a;
    asm("{ .reg .u64 t; cvta.to.shared.u64 t, %1; cvt.u32.u64 %0, t; }"
        : "=r"(a) : "l"(p));
    return a;
}

DEV_INLINE uint32_t h2pack(float a, float b) {
    __half2 h = __floats2half2_rn(a, b);
    return *reinterpret_cast<uint32_t*>(&h);
}

DEV_INLINE void cp_async16(uint32_t dst_smem, const void* src) {
    asm volatile(
        "{\n\t.reg .u64 g;\n\tcvta.to.global.u64 g, %1;\n\t"
        "cp.async.cg.shared.global [%0], [g], 16;\n\t}"
        :: "r"(dst_smem), "l"(src));
}
DEV_INLINE void cp_commit() { asm volatile("cp.async.commit_group;"); }
template <int N> DEV_INLINE void cp_wait() {
    asm volatile("cp.async.wait_group %0;" :: "n"(N));
}

// m16n8k16 fp16 mma, fp32 accumulate
DEV_INLINE void mma_f16(float* c, const uint32_t* a, uint32_t b0, uint32_t b1) {
    asm volatile(
        "mma.sync.aligned.m16n8k16.row.col.f32.f16.f16.f32 "
        "{%0,%1,%2,%3}, {%4,%5,%6,%7}, {%8,%9}, {%0,%1,%2,%3};"
        : "+f"(c[0]), "+f"(c[1]), "+f"(c[2]), "+f"(c[3])
        : "r"(a[0]), "r"(a[1]), "r"(a[2]), "r"(a[3]), "r"(b0), "r"(b1));
}

DEV_INLINE float gelu_exact(float v) {
    return 0.5f * v * (1.0f + erff(v * 0.70710678118654752f));
}

// ---------------- kernel 1: LN partial sums (T split in 2) ----------------
__global__ __launch_bounds__(256) void ln_partial_kernel(const float* __restrict__ x) {
    const int th = blockIdx.x & 1;
    const int fc = (blockIdx.x >> 1) & 1;
    const int b  = blockIdx.x >> 2;
    const int f  = fc * 256 + threadIdx.x;
    const float* xp = x + ((size_t)b * T_ + th * 256) * F_ + f;
    float s = 0.f, ss = 0.f;
#pragma unroll 8
    for (int t = 0; t < 256; t++) {
        float v = xp[(size_t)t * F_];
        s += v;
        ss += v * v;
    }
    g_s[th][b * F_ + f]  = s;
    g_ss[th][b * F_ + f] = ss;
}

// ---------------- kernel 2: pack W into fp16 A-fragment order ----------------
// [m16 (32)][kc (16)][kstep (2)][lane (32)] -> uint4 (8 halfs)
// lane = g*4+tig; regs: r0={W[g][2tig],W[g][2tig+1]}, r1={W[g+8][..]},
//                       r2={W[g][2tig+8],W[g][2tig+9]}, r3={W[g+8][..]}
__global__ __launch_bounds__(256) void pack_w_kernel(const float* __restrict__ W) {
    int lin = blockIdx.x * 256 + threadIdx.x;      // 32768 uint4s
    int lane = lin & 31;
    int kstep = (lin >> 5) & 1;
    int kc = (lin >> 6) & 15;
    int m16 = lin >> 10;
    int g = lane >> 2, tig = lane & 3;
    int mr = m16 * 16 + g;
    int tc = kc * 32 + kstep * 16 + 2 * tig;
    const float* w0 = W + (size_t)mr * T_ + tc;
    const float* w8 = W + (size_t)(mr + 8) * T_ + tc;
    uint4 v;
    v.x = h2pack(w0[0], w0[1]);
    v.y = h2pack(w8[0], w8[1]);
    v.z = h2pack(w0[8], w0[9]);
    v.w = h2pack(w8[8], w8[9]);
    g_WfragH[lin] = v;
}

// ---------------- kernel 3: normalize + transpose into paired fp16 B-frag order ----
// Per (b, ft, kc): [np (8)][kstep (2)][lane (32)] -> uint4
// lane = g*4+tig; t0 = kstep*16 + 2*tig; f0 = np*16+g; f1 = f0+8
// uint4 = { h2(xn[t0][f0],xn[t0+1][f0]), h2(xn[t0+8][f0],xn[t0+9][f0]),
//           h2(xn[t0][f1],xn[t0+1][f1]), h2(xn[t0+8][f1],xn[t0+9][f1]) }
__global__ __launch_bounds__(256) void pack_xn_kernel(const float* __restrict__ x,
                                                      const float* __restrict__ gamma,
                                                      const float* __restrict__ beta) {
    __shared__ float s[32][132];
    __shared__ float s_mu[128], s_rs[128];
    const int kc = blockIdx.x, ft = blockIdx.y, b = blockIdx.z;
    const int tid = threadIdx.x;

    if (tid < 128) {
        int idx = b * F_ + ft * 128 + tid;
        float sm = g_s[0][idx] + g_s[1][idx];
        float sq = g_ss[0][idx] + g_ss[1][idx];
        float mean = sm * (1.0f / T_);
        float var = sq * (1.0f / T_) - mean * mean;
        s_mu[tid] = mean;
        s_rs[tid] = rsqrtf(fmaxf(var, 0.0f) + LN_EPS);
    }
    __syncthreads();

#pragma unroll
    for (int r = 0; r < 4; r++) {
        int i4 = tid + r * 256;
        int tl = i4 >> 5;
        int f4 = (i4 & 31) << 2;
        int gt = kc * 32 + tl;
        float4 v = *reinterpret_cast<const float4*>(
            x + ((size_t)b * T_ + gt) * F_ + ft * 128 + f4);
        float ga = gamma[gt], be = beta[gt];
        s[tl][f4 + 0] = (v.x - s_mu[f4 + 0]) * s_rs[f4 + 0] * ga + be;
        s[tl][f4 + 1] = (v.y - s_mu[f4 + 1]) * s_rs[f4 + 1] * ga + be;
        s[tl][f4 + 2] = (v.z - s_mu[f4 + 2]) * s_rs[f4 + 2] * ga + be;
        s[tl][f4 + 3] = (v.w - s_mu[f4 + 3]) * s_rs[f4 + 3] * ga + be;
    }
    __syncthreads();

    uint4* dst = g_BfragH + (((size_t)b * 4 + ft) * 16 + kc) * 512;
#pragma unroll
    for (int r = 0; r < 2; r++) {
        int o = tid + r * 256;                 // 512 uint4s
        int np = o >> 6;
        int rem = o & 63;
        int kstep = rem >> 5;
        int lane = rem & 31;
        int g = lane >> 2, tig = lane & 3;
        int t0 = kstep * 16 + 2 * tig;
        int f0 = np * 16 + g;
        uint4 v;
        v.x = h2pack(s[t0][f0],     s[t0 + 1][f0]);
        v.y = h2pack(s[t0 + 8][f0], s[t0 + 9][f0]);
        v.z = h2pack(s[t0][f0 + 8],     s[t0 + 1][f0 + 8]);
        v.w = h2pack(s[t0 + 8][f0 + 8], s[t0 + 9][f0 + 8]);
        dst[o] = v;
    }
}

// ---------------- kernel 4: fp16 GEMM + bias + GELU + residual ----------------
__global__ __launch_bounds__(THREADS, 2)
void timemix_gemm_kernel(const float* __restrict__ x,
                         const float* __restrict__ bvec,
                         float* __restrict__ out) {
    extern __shared__ char smem[];
    const int tid = threadIdx.x;
    const int wid = tid >> 5, lane = tid & 31;
    const int wm = wid & 3, wn = wid >> 2;          // 4 x 2 warps (32m x 64f)
    const int bm = blockIdx.x;                      // 0..3
    const int ft = blockIdx.y;                      // 0..3
    const int b = blockIdx.z;

    const uint32_t smem_base = smem_u32(smem);
    const uint4* Bsrc_base = g_BfragH + (((size_t)b * 4 + ft) * 16) * 512;

    auto load_stage = [&](int kc) {
        uint32_t sA = smem_base + (kc & (NSTAGE - 1)) * STAGE_B;
        uint32_t sB = sA + A_STAGE_B;
#pragma unroll
        for (int r = 0; r < 2; r++) {               // A: 512 uint4s
            int i = tid + r * 256;
            int m16l = i >> 6;                      // 8 m16 blocks
            int off = i & 63;                       // kstep*32 + lane
            const uint4* src = g_WfragH + ((size_t)(bm * 8 + m16l) * 16 + kc) * 64 + off;
            cp_async16(sA + i * 16, src);
        }
        const uint4* Bsrc = Bsrc_base + (size_t)kc * 512;
#pragma unroll
        for (int r = 0; r < 2; r++) {               // B: 512 uint4s
            int i = tid + r * 256;
            cp_async16(sB + i * 16, Bsrc + i);
        }
        cp_commit();
    };

    float acc[2][8][4];
#pragma unroll
    for (int i = 0; i < 2; i++)
#pragma unroll
        for (int j = 0; j < 8; j++)
#pragma unroll
            for (int r = 0; r < 4; r++) acc[i][j][r] = 0.0f;

    load_stage(0);
    load_stage(1);
    load_stage(2);

    for (int kc = 0; kc < NKC; kc++) {
        if (kc + 3 < NKC) cp_wait<2>();
        else if (kc + 2 < NKC) cp_wait<1>();
        else cp_wait<0>();
        __syncthreads();

        const uint4* sA = reinterpret_cast<const uint4*>(smem + (kc & (NSTAGE - 1)) * STAGE_B);
        const uint4* sB = reinterpret_cast<const uint4*>(
            smem + (kc & (NSTAGE - 1)) * STAGE_B + A_STAGE_B);

#pragma unroll
        for (int kstep = 0; kstep < 2; kstep++) {
            uint32_t a[2][4];
#pragma unroll
            for (int i = 0; i < 2; i++) {
                uint4 v = sA[((wm * 2 + i) * 2 + kstep) * 32 + lane];
                a[i][0] = v.x; a[i][1] = v.y; a[i][2] = v.z; a[i][3] = v.w;
            }
            uint4 bf[4];
#pragma unroll
            for (int jp = 0; jp < 4; jp++)
                bf[jp] = sB[((wn * 4 + jp) * 2 + kstep) * 32 + lane];
#pragma unroll
            for (int i = 0; i < 2; i++)
#pragma unroll
                for (int jp = 0; jp < 4; jp++) {
                    mma_f16(acc[i][2 * jp + 0], a[i], bf[jp].x, bf[jp].y);
                    mma_f16(acc[i][2 * jp + 1], a[i], bf[jp].z, bf[jp].w);
                }
        }

        if (kc + 3 < NKC) load_stage(kc + 3);   // write buffer (kc+3)&3 == (kc-1)&3, safe post-barrier
    }

    // ---- epilogue: bias + exact GELU + residual ----
    const int g = lane >> 2, tig = lane & 3;
    const int m_warp = bm * 128 + wm * 32;
    const int f_warp = ft * 128 + wn * 64;
#pragma unroll
    for (int i = 0; i < 2; i++) {
#pragma unroll
        for (int h = 0; h < 2; h++) {
            int m = m_warp + i * 16 + g + 8 * h;
            float bv = bvec[m];
            const float* xr = x + ((size_t)b * M_ + m) * F_ + f_warp;
            float* yr = out + ((size_t)b * M_ + m) * F_ + f_warp;
#pragma unroll
            for (int j = 0; j < 8; j++) {
                int fo = j * 8 + tig * 2;
                float2 xv = *reinterpret_cast<const float2*>(xr + fo);
                float2 o;
                o.x = gelu_exact(acc[i][j][2 * h + 0] + bv) + xv.x;
                o.y = gelu_exact(acc[i][j][2 * h + 1] + bv) + xv.y;
                *reinterpret_cast<float2*>(yr + fo) = o;
            }
        }
    }
}

// ---------------- launch ----------------
extern "C" void kernel_launch(void* const* d_in, const int* in_sizes, int n_in,
                              void* d_out, int out_size) {
    const float* x     = (const float*)d_in[0];
    const float* gamma = (const float*)d_in[1];
    const float* beta  = (const float*)d_in[2];
    const float* W     = (const float*)d_in[3];
    const float* bvec  = (const float*)d_in[4];
    float* out = (float*)d_out;

    cudaFuncSetAttribute(timemix_gemm_kernel,
                         cudaFuncAttributeMaxDynamicSharedMemorySize, SMEM_BYTES);

    ln_partial_kernel<<<B_ * 2 * 2, 256>>>(x);
    pack_w_kernel<<<32768 / 256, 256>>>(W);
    {
        dim3 grid(NKC, F_ / 128, B_);
        pack_xn_kernel<<<grid, 256>>>(x, gamma, beta);
    }
    {
        dim3 grid(M_ / BM, F_ / BN, B_);   // (4, 4, 128)
        timemix_gemm_kernel<<<grid, THREADS, SMEM_BYTES>>>(x, bvec, out);
    }
}

// round 7
// speedup vs baseline: 1.8003x; 1.0629x over previous
#include <cuda_runtime.h>
#include <cuda_fp16.h>
#include <cstdint>
#include <math.h>

#define DEV_INLINE __device__ __forceinline__

// Problem dims (fixed by the dataset)
constexpr int B_ = 128, T_ = 512, F_ = 512, M_ = 512;
constexpr float LN_EPS = 1e-5f;

// GEMM tiling: CTA 128(m) x 128(f) x 64(k); 8 warps of 32x64; fp16 mma k16
constexpr int BM = 128, BN = 128, BK = 64;
constexpr int NKC = T_ / BK;     // 8 k-chunks
constexpr int THREADS = 256;
constexpr int NSTAGE = 3;

// Stage sizes in BYTES (fp16 operands)
constexpr int A_STAGE_B = BM * BK * 2;            // 16384 B
constexpr int B_STAGE_B = BN * BK * 2;            // 16384 B
constexpr int STAGE_B   = A_STAGE_B + B_STAGE_B;  // 32 KB
constexpr int SMEM_BYTES = NSTAGE * STAGE_B;      // 96 KB

// Device scratch (no allocation allowed)
__device__ float g_s[4][B_ * F_];                 // LN partial sums (T quarters)
__device__ float g_ss[4][B_ * F_];
__device__ uint4 g_WfragH[32 * 16 * 2 * 32];      // 512KB: [m16][kc16][kstep2][lane]
__device__ uint4 g_BfragH[(size_t)B_ * 4 * 16 * 512];  // 64MB: [b][ft][kc16][np][kstep2][lane]

// ---------------- helpers ----------------
DEV_INLINE uint32_t smem_u32(const void* p) {
    uint32_t a;
    asm("{ .reg .u64 t; cvta.to.shared.u64 t, %1; cvt.u32.u64 %0, t; }"
        : "=r"(a) : "l"(p));
    return a;
}

DEV_INLINE uint32_t h2pack(float a, float b) {
    __half2 h = __floats2half2_rn(a, b);
    return *reinterpret_cast<uint32_t*>(&h);
}

DEV_INLINE void cp_async16(uint32_t dst_smem, const void* src) {
    asm volatile(
        "{\n\t.reg .u64 g;\n\tcvta.to.global.u64 g, %1;\n\t"
        "cp.async.cg.shared.global [%0], [g], 16;\n\t}"
        :: "r"(dst_smem), "l"(src));
}
DEV_INLINE void cp_commit() { asm volatile("cp.async.commit_group;"); }
template <int N> DEV_INLINE void cp_wait() {
    asm volatile("cp.async.wait_group %0;" :: "n"(N));
}

// m16n8k16 fp16 mma, fp32 accumulate
DEV_INLINE void mma_f16(float* c, const uint32_t* a, uint32_t b0, uint32_t b1) {
    asm volatile(
        "mma.sync.aligned.m16n8k16.row.col.f32.f16.f16.f32 "
        "{%0,%1,%2,%3}, {%4,%5,%6,%7}, {%8,%9}, {%0,%1,%2,%3};"
        : "+f"(c[0]), "+f"(c[1]), "+f"(c[2]), "+f"(c[3])
        : "r"(a[0]), "r"(a[1]), "r"(a[2]), "r"(a[3]), "r"(b0), "r"(b1));
}

DEV_INLINE float gelu_exact(float v) {
    return 0.5f * v * (1.0f + erff(v * 0.70710678118654752f));
}

// ---------------- kernel 1: LN partial sums (T split in 4) ----------------
__global__ __launch_bounds__(256) void ln_partial_kernel(const float* __restrict__ x) {
    const int tq = blockIdx.x & 3;             // T quarter
    const int fc = (blockIdx.x >> 2) & 1;      // f chunk of 256
    const int b  = blockIdx.x >> 3;
    const int f  = fc * 256 + threadIdx.x;
    const float* xp = x + ((size_t)b * T_ + tq * 128) * F_ + f;
    float s = 0.f, ss = 0.f;
#pragma unroll 8
    for (int t = 0; t < 128; t++) {
        float v = xp[(size_t)t * F_];
        s += v;
        ss += v * v;
    }
    g_s[tq][b * F_ + f]  = s;
    g_ss[tq][b * F_ + f] = ss;
}

// ---------------- kernel 2: pack W into fp16 A-fragment order ----------------
// [m16 (32)][kc16 (16)][kstep (2)][lane (32)] -> uint4 (8 halfs)
__global__ __launch_bounds__(256) void pack_w_kernel(const float* __restrict__ W) {
    int lin = blockIdx.x * 256 + threadIdx.x;      // 32768 uint4s
    int lane = lin & 31;
    int kstep = (lin >> 5) & 1;
    int kc = (lin >> 6) & 15;
    int m16 = lin >> 10;
    int g = lane >> 2, tig = lane & 3;
    int mr = m16 * 16 + g;
    int tc = kc * 32 + kstep * 16 + 2 * tig;
    const float* w0 = W + (size_t)mr * T_ + tc;
    const float* w8 = W + (size_t)(mr + 8) * T_ + tc;
    uint4 v;
    v.x = h2pack(w0[0], w0[1]);
    v.y = h2pack(w8[0], w8[1]);
    v.z = h2pack(w0[8], w0[9]);
    v.w = h2pack(w8[8], w8[9]);
    g_WfragH[lin] = v;
}

// ---------------- kernel 3: normalize + transpose into paired fp16 B-frag order ----
// Per (b, ft, kc16): [np (8)][kstep (2)][lane (32)] -> uint4
__global__ __launch_bounds__(256) void pack_xn_kernel(const float* __restrict__ x,
                                                      const float* __restrict__ gamma,
                                                      const float* __restrict__ beta) {
    __shared__ float s[32][132];
    __shared__ float s_mu[128], s_rs[128];
    const int kc = blockIdx.x, ft = blockIdx.y, b = blockIdx.z;
    const int tid = threadIdx.x;

    if (tid < 128) {
        int idx = b * F_ + ft * 128 + tid;
        float sm = g_s[0][idx] + g_s[1][idx] + g_s[2][idx] + g_s[3][idx];
        float sq = g_ss[0][idx] + g_ss[1][idx] + g_ss[2][idx] + g_ss[3][idx];
        float mean = sm * (1.0f / T_);
        float var = sq * (1.0f / T_) - mean * mean;
        s_mu[tid] = mean;
        s_rs[tid] = rsqrtf(fmaxf(var, 0.0f) + LN_EPS);
    }
    __syncthreads();

#pragma unroll
    for (int r = 0; r < 4; r++) {
        int i4 = tid + r * 256;
        int tl = i4 >> 5;
        int f4 = (i4 & 31) << 2;
        int gt = kc * 32 + tl;
        float4 v = *reinterpret_cast<const float4*>(
            x + ((size_t)b * T_ + gt) * F_ + ft * 128 + f4);
        float ga = gamma[gt], be = beta[gt];
        s[tl][f4 + 0] = (v.x - s_mu[f4 + 0]) * s_rs[f4 + 0] * ga + be;
        s[tl][f4 + 1] = (v.y - s_mu[f4 + 1]) * s_rs[f4 + 1] * ga + be;
        s[tl][f4 + 2] = (v.z - s_mu[f4 + 2]) * s_rs[f4 + 2] * ga + be;
        s[tl][f4 + 3] = (v.w - s_mu[f4 + 3]) * s_rs[f4 + 3] * ga + be;
    }
    __syncthreads();

    uint4* dst = g_BfragH + (((size_t)b * 4 + ft) * 16 + kc) * 512;
#pragma unroll
    for (int r = 0; r < 2; r++) {
        int o = tid + r * 256;                 // 512 uint4s
        int np = o >> 6;
        int rem = o & 63;
        int kstep = rem >> 5;
        int lane = rem & 31;
        int g = lane >> 2, tig = lane & 3;
        int t0 = kstep * 16 + 2 * tig;
        int f0 = np * 16 + g;
        uint4 v;
        v.x = h2pack(s[t0][f0],     s[t0 + 1][f0]);
        v.y = h2pack(s[t0 + 8][f0], s[t0 + 9][f0]);
        v.z = h2pack(s[t0][f0 + 8],     s[t0 + 1][f0 + 8]);
        v.w = h2pack(s[t0 + 8][f0 + 8], s[t0 + 9][f0 + 8]);
        dst[o] = v;
    }
}

// ---------------- kernel 4: fp16 GEMM + bias + GELU + residual ----------------
// BK=64: smem A = [m16l (8)][ks (4)][lane], B = [np (8)][ks (4)][lane] (uint4 units)
__global__ __launch_bounds__(THREADS, 2)
void timemix_gemm_kernel(const float* __restrict__ x,
                         const float* __restrict__ bvec,
                         float* __restrict__ out) {
    extern __shared__ char smem[];
    const int tid = threadIdx.x;
    const int wid = tid >> 5, lane = tid & 31;
    const int wm = wid & 3, wn = wid >> 2;          // 4 x 2 warps (32m x 64f)
    const int bm = blockIdx.x;                      // 0..3
    const int ft = blockIdx.y;                      // 0..3
    const int b = blockIdx.z;

    const uint32_t smem_base = smem_u32(smem);
    const uint4* Bsrc_base = g_BfragH + (((size_t)b * 4 + ft) * 16) * 512;

    // stage for k-chunk kc8 (64 k's): A chunks kchunk = kc8*4 + ks
    auto load_stage = [&](int kc8) {
        uint32_t sA = smem_base + (kc8 % NSTAGE) * STAGE_B;
        uint32_t sB = sA + A_STAGE_B;
#pragma unroll
        for (int r = 0; r < 4; r++) {               // A: 1024 uint4s
            int i = tid + r * 256;
            int m16l = i >> 7;                      // 8 m16 blocks
            int off = i & 127;                      // ks*32 + lane
            const uint4* src = g_WfragH + (((size_t)(bm * 8 + m16l) * 32) + kc8 * 4) * 32 + off;
            cp_async16(sA + i * 16, src);
        }
#pragma unroll
        for (int r = 0; r < 4; r++) {               // B: 1024 uint4s
            int i = tid + r * 256;
            int np = i >> 7;
            int rem = i & 127;
            int ks = rem >> 5;
            int ln = rem & 31;
            const uint4* src = Bsrc_base + (size_t)(2 * kc8 + (ks >> 1)) * 512
                               + np * 64 + (ks & 1) * 32 + ln;
            cp_async16(sB + i * 16, src);
        }
        cp_commit();
    };

    float acc[2][8][4];
#pragma unroll
    for (int i = 0; i < 2; i++)
#pragma unroll
        for (int j = 0; j < 8; j++)
#pragma unroll
            for (int r = 0; r < 4; r++) acc[i][j][r] = 0.0f;

    load_stage(0);
    load_stage(1);

    for (int kc = 0; kc < NKC; kc++) {
        if (kc + 1 < NKC) cp_wait<1>(); else cp_wait<0>();
        __syncthreads();

        const uint4* sA = reinterpret_cast<const uint4*>(smem + (kc % NSTAGE) * STAGE_B);
        const uint4* sB = reinterpret_cast<const uint4*>(
            smem + (kc % NSTAGE) * STAGE_B + A_STAGE_B);

#pragma unroll
        for (int kstep = 0; kstep < 4; kstep++) {
            uint32_t a[2][4];
#pragma unroll
            for (int i = 0; i < 2; i++) {
                uint4 v = sA[((wm * 2 + i) * 4 + kstep) * 32 + lane];
                a[i][0] = v.x; a[i][1] = v.y; a[i][2] = v.z; a[i][3] = v.w;
            }
            uint4 bf[4];
#pragma unroll
            for (int jp = 0; jp < 4; jp++)
                bf[jp] = sB[((wn * 4 + jp) * 4 + kstep) * 32 + lane];
#pragma unroll
            for (int i = 0; i < 2; i++)
#pragma unroll
                for (int jp = 0; jp < 4; jp++) {
                    mma_f16(acc[i][2 * jp + 0], a[i], bf[jp].x, bf[jp].y);
                    mma_f16(acc[i][2 * jp + 1], a[i], bf[jp].z, bf[jp].w);
                }
        }

        // prefetch kc+2: writes stage (kc+2)%3 == (kc-1)%3, consumed before top barrier
        if (kc + 2 < NKC) load_stage(kc + 2);
    }

    // ---- epilogue: bias + exact GELU + residual ----
    const int g = lane >> 2, tig = lane & 3;
    const int m_warp = bm * 128 + wm * 32;
    const int f_warp = ft * 128 + wn * 64;
#pragma unroll
    for (int i = 0; i < 2; i++) {
#pragma unroll
        for (int h = 0; h < 2; h++) {
            int m = m_warp + i * 16 + g + 8 * h;
            float bv = bvec[m];
            const float* xr = x + ((size_t)b * M_ + m) * F_ + f_warp;
            float* yr = out + ((size_t)b * M_ + m) * F_ + f_warp;
#pragma unroll
            for (int j = 0; j < 8; j++) {
                int fo = j * 8 + tig * 2;
                float2 xv = *reinterpret_cast<const float2*>(xr + fo);
                float2 o;
                o.x = gelu_exact(acc[i][j][2 * h + 0] + bv) + xv.x;
                o.y = gelu_exact(acc[i][j][2 * h + 1] + bv) + xv.y;
                *reinterpret_cast<float2*>(yr + fo) = o;
            }
        }
    }
}

// ---------------- launch ----------------
extern "C" void kernel_launch(void* const* d_in, const int* in_sizes, int n_in,
                              void* d_out, int out_size) {
    const float* x     = (const float*)d_in[0];
    const float* gamma = (const float*)d_in[1];
    const float* beta  = (const float*)d_in[2];
    const float* W     = (const float*)d_in[3];
    const float* bvec  = (const float*)d_in[4];
    float* out = (float*)d_out;

    cudaFuncSetAttribute(timemix_gemm_kernel,
                         cudaFuncAttributeMaxDynamicSharedMemorySize, SMEM_BYTES);

    ln_partial_kernel<<<B_ * 4 * 2, 256>>>(x);
    pack_w_kernel<<<32768 / 256, 256>>>(W);
    {
        dim3 grid(16, F_ / 128, B_);
        pack_xn_kernel<<<grid, 256>>>(x, gamma, beta);
    }
    {
        dim3 grid(M_ / BM, F_ / BN, B_);   // (4, 4, 128)
        timemix_gemm_kernel<<<grid, THREADS, SMEM_BYTES>>>(x, bvec, out);
    }
}